// round 11
// baseline (speedup 1.0000x reference)
#include <cuda_runtime.h>
#include <cuda_bf16.h>
#include <cstdint>

#define ROWS6 393216
#define BATCH 65536
#define EPS_LN 1e-5f

// ---------------- scratch globals (allocation-free rule) -------------------
__device__ __align__(16) float g_qkv[(size_t)ROWS6 * 384];
__device__ __align__(16) float g_n[(size_t)ROWS6 * 256];
__device__ __align__(16) __nv_bfloat16 g_xh[(size_t)ROWS6 * 128], g_xl[(size_t)ROWS6 * 128];
__device__ __align__(16) __nv_bfloat16 g_ath[(size_t)ROWS6 * 128], g_atl[(size_t)ROWS6 * 128];
__device__ __align__(16) __nv_bfloat16 g_A2h[(size_t)BATCH * 3072], g_A2l[(size_t)BATCH * 3072];
__device__ __align__(16) __nv_bfloat16 g_WcT_hi[384 * 128], g_WcT_lo[384 * 128];
__device__ __align__(16) __nv_bfloat16 g_WfT_hi[256 * 256], g_WfT_lo[256 * 256];   // g1-scaled
__device__ __align__(16) __nv_bfloat16 g_WsT_hi[256 * 3072], g_WsT_lo[256 * 3072];
__device__ float g_bc[384], g_uf[256], g_cf[256];
__device__ float g_msum[ROWS6], g_msumsq[ROWS6], g_mu1[ROWS6], g_rs1[ROWS6];

// ---------------- helpers --------------------------------------------------
__device__ __forceinline__ uint32_t smem_u32(const void* p) {
    uint32_t a;
    asm("{ .reg .u64 t; cvta.to.shared.u64 t, %1; cvt.u32.u64 %0, t; }" : "=r"(a) : "l"(p));
    return a;
}
__device__ __forceinline__ void ldsm4(uint32_t& r0, uint32_t& r1, uint32_t& r2, uint32_t& r3,
                                      uint32_t addr) {
    asm volatile("ldmatrix.sync.aligned.m8n8.x4.shared.b16 {%0,%1,%2,%3}, [%4];"
                 : "=r"(r0), "=r"(r1), "=r"(r2), "=r"(r3) : "r"(addr));
}
__device__ __forceinline__ void mma16816(float* d, const uint32_t* a, const uint32_t* b) {
    asm volatile("mma.sync.aligned.m16n8k16.row.col.f32.bf16.bf16.f32 "
                 "{%0,%1,%2,%3}, {%4,%5,%6,%7}, {%8,%9}, {%0,%1,%2,%3};"
                 : "+f"(d[0]), "+f"(d[1]), "+f"(d[2]), "+f"(d[3])
                 : "r"(a[0]), "r"(a[1]), "r"(a[2]), "r"(a[3]), "r"(b[0]), "r"(b[1]));
}
__device__ __forceinline__ void cpasync16(uint32_t dst, const void* src) {
    asm volatile("cp.async.cg.shared.global [%0], [%1], 16;" :: "r"(dst), "l"(src));
}
__device__ __forceinline__ void cpcommit() {
    asm volatile("cp.async.commit_group;" ::: "memory");
}
__device__ __forceinline__ void bf16split(float v, __nv_bfloat16& h, __nv_bfloat16& l) {
    h = __float2bfloat16(v);
    l = __float2bfloat16(v - __bfloat162float(h));
}

// ---------------------------------------------------------------------------
// GEMM driver: 256 thr, 2 CTAs/SM. BM=128 x BN=128, BK=16, 2-stage cp.async.
// A hi/lo pointers supplied per (row,k) by asrc; B pre-split K-major hi/lo.
// 3-term split: D = ah*bh + ah*bl + al*bh.
// smem: [2 stages][4 bufs: Ah,Al,Bh,Bl][128 rows][24 bf16 pad] = 48KB.
// ---------------------------------------------------------------------------
template <class ASrc, class Epi>
__device__ __forceinline__ void gemm_cp(
    ASrc asrc,
    const __nv_bfloat16* __restrict__ Bh, const __nv_bfloat16* __restrict__ Bl, int n0,
    int ktot, int nchunk, Epi epi)
{
    __shared__ __align__(16) __nv_bfloat16 sm[2][4][128][24];

    const int tid = threadIdx.x, lane = tid & 31, wid = tid >> 5;
    const int m_base = (wid & 1) * 64, n_base = (wid >> 1) * 32;
    const int arow = lane & 15, acol = (lane >> 4) * 8;
    const int lrow = tid >> 1, lh = (tid & 1) * 8;

    const uint32_t s0 = smem_u32(&sm[0][0][0][0]);
    const __nv_bfloat16* gs2 = Bh + (size_t)(n0 + lrow) * ktot + lh;
    const __nv_bfloat16* gs3 = Bl + (size_t)(n0 + lrow) * ktot + lh;
    const uint32_t dstb = s0 + (uint32_t)(lrow * 24 + lh) * 2;

    float d[4][4][4];
#pragma unroll
    for (int mi = 0; mi < 4; ++mi)
#pragma unroll
        for (int ni = 0; ni < 4; ++ni)
#pragma unroll
            for (int e = 0; e < 4; ++e) d[mi][ni][e] = 0.f;

    // prologue: stages 0,1
    {
        const __nv_bfloat16 *ph, *pl;
        asrc(lrow, lh, ph, pl);
        cpasync16(dstb,         ph);
        cpasync16(dstb + 6144,  pl);
        cpasync16(dstb + 12288, gs2);
        cpasync16(dstb + 18432, gs3);
        cpcommit();
        asrc(lrow, 16 + lh, ph, pl);
        cpasync16(dstb + 24576, ph);
        cpasync16(dstb + 30720, pl);
        cpasync16(dstb + 36864, gs2 + 16);
        cpasync16(dstb + 43008, gs3 + 16);
        cpcommit();
    }

    for (int c = 0; c < nchunk; ++c) {
        if (c == nchunk - 1)
            asm volatile("cp.async.wait_group 0;" ::: "memory");
        else
            asm volatile("cp.async.wait_group 1;" ::: "memory");
        __syncthreads();

        const int st = c & 1;
        const uint32_t bAh = s0 + (uint32_t)(st * 4 + 0) * 6144;
        const uint32_t bAl = s0 + (uint32_t)(st * 4 + 1) * 6144;
        const uint32_t bBh = s0 + (uint32_t)(st * 4 + 2) * 6144;
        const uint32_t bBl = s0 + (uint32_t)(st * 4 + 3) * 6144;

        uint32_t bh_[4][2], bl_[4][2];
#pragma unroll
        for (int nt = 0; nt < 2; ++nt) {
            const uint32_t off = (uint32_t)((n_base + nt * 16 + arow) * 24 + acol) * 2;
            uint32_t r0, r1, r2, r3;
            ldsm4(r0, r1, r2, r3, bBh + off);
            bh_[2 * nt][0] = r0; bh_[2 * nt][1] = r2;
            bh_[2 * nt + 1][0] = r1; bh_[2 * nt + 1][1] = r3;
            ldsm4(r0, r1, r2, r3, bBl + off);
            bl_[2 * nt][0] = r0; bl_[2 * nt][1] = r2;
            bl_[2 * nt + 1][0] = r1; bl_[2 * nt + 1][1] = r3;
        }
        uint32_t af[4][4];
#pragma unroll
        for (int mi = 0; mi < 4; ++mi) {
            const uint32_t off = (uint32_t)((m_base + mi * 16 + arow) * 24 + acol) * 2;
            ldsm4(af[mi][0], af[mi][1], af[mi][2], af[mi][3], bAh + off);
        }
#pragma unroll
        for (int mi = 0; mi < 4; ++mi)
#pragma unroll
            for (int ni = 0; ni < 4; ++ni) {
                mma16816(d[mi][ni], af[mi], bh_[ni]);
                mma16816(d[mi][ni], af[mi], bl_[ni]);
            }
#pragma unroll
        for (int mi = 0; mi < 4; ++mi) {
            const uint32_t off = (uint32_t)((m_base + mi * 16 + arow) * 24 + acol) * 2;
            ldsm4(af[mi][0], af[mi][1], af[mi][2], af[mi][3], bAl + off);
        }
#pragma unroll
        for (int mi = 0; mi < 4; ++mi)
#pragma unroll
            for (int ni = 0; ni < 4; ++ni)
                mma16816(d[mi][ni], af[mi], bh_[ni]);

        __syncthreads();
        if (c + 2 < nchunk) {
            const int kb = (c + 2) * 16;
            const uint32_t db = dstb + (uint32_t)(st * 4) * 6144;
            const __nv_bfloat16 *ph, *pl;
            asrc(lrow, kb + lh, ph, pl);
            cpasync16(db,         ph);
            cpasync16(db + 6144,  pl);
            cpasync16(db + 12288, gs2 + kb);
            cpasync16(db + 18432, gs3 + kb);
            cpcommit();
        } else {
            cpcommit();
        }
    }

#pragma unroll
    for (int mi = 0; mi < 4; ++mi)
#pragma unroll
        for (int ni = 0; ni < 4; ++ni) {
            const int r0 = m_base + mi * 16 + (lane >> 2);
            const int col = n_base + ni * 8 + 2 * (lane & 3);
            epi(r0, col, d[mi][ni][0], d[mi][ni][1]);
            epi(r0 + 8, col, d[mi][ni][2], d[mi][ni][3]);
        }
}

// ---------------------------------------------------------------------------
// k_prep: weight splits. WfT is pre-scaled by g1 (LN1 fold).
// ---------------------------------------------------------------------------
__global__ void __launch_bounds__(256) k_prep(
    const float* __restrict__ W0, const float* __restrict__ W1,
    const float* __restrict__ W2, const float* __restrict__ W3,
    const float* __restrict__ b0, const float* __restrict__ b1,
    const float* __restrict__ b2, const float* __restrict__ b3,
    const float* __restrict__ Wf, const float* __restrict__ Ws,
    const float* __restrict__ g1)
{
    const int i = blockIdx.x * 256 + threadIdx.x;
    if (i < 49152) {                       // WcT [384 n][128 k]
        int n = i >> 7, k = i & 127;
        int h = n / 96, cc = n - h * 96;
        const float* Wh = (h == 0) ? W0 : (h == 1) ? W1 : (h == 2) ? W2 : W3;
        bf16split(Wh[k * 96 + cc], g_WcT_hi[i], g_WcT_lo[i]);
    }
    if (i < 384) {
        int h = i / 96, cc = i - h * 96;
        g_bc[i] = ((h == 0) ? b0 : (h == 1) ? b1 : (h == 2) ? b2 : b3)[cc];
    }
    if (i < 65536) {                       // WfT' [256 n][256 k] = g1[k]*Wf[k][n]
        int n = i >> 8, k = i & 255;
        bf16split(g1[k] * Wf[(size_t)k * 256 + n], g_WfT_hi[i], g_WfT_lo[i]);
    }
    if (i < 786432) {                      // WsT [256 n][3072 k]
        int n = i / 3072, k = i - n * 3072;
        bf16split(Ws[(size_t)k * 256 + n], g_WsT_hi[i], g_WsT_lo[i]);
    }
}

// k_vec: uf[n] = sum_k g1[k]*Wf[k][n];  cf[n] = sum_k be1[k]*Wf[k][n] + bf[n].
__global__ void __launch_bounds__(256) k_vec(
    const float* __restrict__ Wf, const float* __restrict__ g1,
    const float* __restrict__ be1, const float* __restrict__ bf)
{
    const int n = threadIdx.x;
    float u = 0.f, c = 0.f;
    for (int k = 0; k < 256; ++k) {
        float w = Wf[(size_t)k * 256 + n];
        u = fmaf(g1[k], w, u);
        c = fmaf(be1[k], w, c);
    }
    g_uf[n] = u;
    g_cf[n] = c + bf[n];
}

// ---------------------------------------------------------------------------
// k_cvtx: x fp32 -> bf16 hi/lo.
// ---------------------------------------------------------------------------
__global__ void __launch_bounds__(256) k_cvtx(const float* __restrict__ x)
{
    const size_t i = (size_t)blockIdx.x * 256 + threadIdx.x;   // float4 index
    float4 v = ((const float4*)x)[i];
    __nv_bfloat16 h0, l0, h1, l1, h2, l2, h3, l3;
    bf16split(v.x, h0, l0); bf16split(v.y, h1, l1);
    bf16split(v.z, h2, l2); bf16split(v.w, h3, l3);
    __nv_bfloat162 hp0 = __halves2bfloat162(h0, h1), hp1 = __halves2bfloat162(h2, h3);
    __nv_bfloat162 lp0 = __halves2bfloat162(l0, l1), lp1 = __halves2bfloat162(l2, l3);
    ((uint2*)g_xh)[i] = make_uint2(*(uint32_t*)&hp0, *(uint32_t*)&hp1);
    ((uint2*)g_xl)[i] = make_uint2(*(uint32_t*)&lp0, *(uint32_t*)&lp1);
}

// ---------------------------------------------------------------------------
// k_qkv: g_qkv = x @ Wcat + bcat.  grid(x = 3 n-tiles, y = 3072 m-tiles).
// ---------------------------------------------------------------------------
__global__ void __launch_bounds__(256, 2) k_qkv()
{
    const int n0 = blockIdx.x * 128, row0 = blockIdx.y * 128;
    gemm_cp(
        [&](int row, int k, const __nv_bfloat16*& ph, const __nv_bfloat16*& pl) {
            size_t o = (size_t)(row0 + row) * 128 + k;
            ph = g_xh + o; pl = g_xl + o;
        },
        g_WcT_hi, g_WcT_lo, n0, 128, 8,
        [&](int row, int col, float v0, float v1) {
            float2 t;
            t.x = v0 + g_bc[n0 + col];
            t.y = v1 + g_bc[n0 + col + 1];
            *(float2*)(g_qkv + (size_t)(row0 + row) * 384 + n0 + col) = t;
        });
}

// ---------------------------------------------------------------------------
// k_attn2: attention -> attn hi/lo + m stats + mu1/rs1.
// ---------------------------------------------------------------------------
__global__ void __launch_bounds__(256) k_attn2(const float* __restrict__ x)
{
    const int tid = threadIdx.x, w = tid >> 5, lane = tid & 31;
    const int b = blockIdx.x * 8 + w;

    float qv[6][12];
#pragma unroll
    for (int s = 0; s < 6; ++s)
#pragma unroll
        for (int jj = 0; jj < 12; ++jj)
            qv[s][jj] = g_qkv[((size_t)b * 6 + s) * 384 + jj * 32 + lane];

    float ssum[6], ssq[6];
#pragma unroll
    for (int s = 0; s < 6; ++s) {
        float a = 0.f, q = 0.f;
#pragma unroll
        for (int i = 0; i < 4; ++i) {
            float v = x[(size_t)b * 768 + s * 128 + lane + 32 * i];
            a += v; q += v * v;
        }
        ssum[s] = a; ssq[s] = q;
    }

#pragma unroll
    for (int h = 0; h < 4; ++h) {
#pragma unroll
        for (int qi = 0; qi < 6; ++qi) {
            float o = 0.f;
#pragma unroll
            for (int ki = 0; ki < 6; ++ki) {
                float p = qv[qi][3 * h] * qv[ki][3 * h + 1];
#pragma unroll
                for (int off = 16; off > 0; off >>= 1)
                    p += __shfl_xor_sync(0xffffffffu, p, off);
                o = fmaf(p, qv[ki][3 * h + 2], o);
            }
            const size_t idx = ((size_t)b * 6 + qi) * 128 + h * 32 + lane;
            __nv_bfloat16 hh, ll;
            bf16split(o, hh, ll);
            g_ath[idx] = hh;
            g_atl[idx] = ll;
            ssum[qi] += o;
            ssq[qi] += o * o;
        }
    }

#pragma unroll
    for (int s = 0; s < 6; ++s) {
        float a = ssum[s], q = ssq[s];
#pragma unroll
        for (int off = 16; off > 0; off >>= 1) {
            a += __shfl_xor_sync(0xffffffffu, a, off);
            q += __shfl_xor_sync(0xffffffffu, q, off);
        }
        if (lane == 0) {
            const int r = b * 6 + s;
            g_msum[r] = a;
            g_msumsq[r] = q;
            const float mu = a * (1.f / 256.f);
            const float var = q * (1.f / 256.f) - mu * mu;
            g_mu1[r] = mu;
            g_rs1[r] = rsqrtf(var + EPS_LN);
        }
    }
}

// ---------------------------------------------------------------------------
// k_ln1: g_n = rs1*( m @ Wf' - mu1*uf ) + cf.   A = raw m hi/lo.
// grid(x = 2 n-tiles, y = 3072 m-tiles).
// ---------------------------------------------------------------------------
__global__ void __launch_bounds__(256, 2) k_ln1()
{
    const int n0 = blockIdx.x * 128, row0 = blockIdx.y * 128;
    gemm_cp(
        [&](int row, int k, const __nv_bfloat16*& ph, const __nv_bfloat16*& pl) {
            const size_t r = (size_t)(row0 + row);
            if (k < 128) { size_t o = r * 128 + k;       ph = g_xh + o;  pl = g_xl + o; }
            else         { size_t o = r * 128 + k - 128; ph = g_ath + o; pl = g_atl + o; }
        },
        g_WfT_hi, g_WfT_lo, n0, 256, 16,
        [&](int row, int col, float v0, float v1) {
            const int r = row0 + row;
            const float mu = g_mu1[r], rs = g_rs1[r];
            const int c0 = n0 + col;
            float2 t;
            t.x = rs * (v0 - mu * g_uf[c0])     + g_cf[c0];
            t.y = rs * (v1 - mu * g_uf[c0 + 1]) + g_cf[c0 + 1];
            *(float2*)(g_n + (size_t)r * 256 + c0) = t;
        });
}

// ---------------------------------------------------------------------------
// k_cvt2: LN2 stats over concat(n,m) + write A2 (bf16 hi/lo, g2/be2 folded).
// One warp per row r = b*6+s.  A2 k-order per row: [n 256][x 128][attn 128].
// ---------------------------------------------------------------------------
__global__ void __launch_bounds__(256) k_cvt2(
    const float* __restrict__ x,
    const float* __restrict__ g2, const float* __restrict__ be2)
{
    const int w = threadIdx.x >> 5, lane = threadIdx.x & 31;
    const int r = blockIdx.x * 8 + w;
    const int b = r / 6, s = r - b * 6;

    const float4* pn = (const float4*)(g_n + (size_t)r * 256);
    float4 n0v = pn[lane], n1v = pn[32 + lane];
    float sum = n0v.x + n0v.y + n0v.z + n0v.w + n1v.x + n1v.y + n1v.z + n1v.w;
    float sq  = n0v.x * n0v.x + n0v.y * n0v.y + n0v.z * n0v.z + n0v.w * n0v.w
              + n1v.x * n1v.x + n1v.y * n1v.y + n1v.z * n1v.z + n1v.w * n1v.w;
#pragma unroll
    for (int off = 16; off > 0; off >>= 1) {
        sum += __shfl_xor_sync(0xffffffffu, sum, off);
        sq  += __shfl_xor_sync(0xffffffffu, sq, off);
    }
    const float tot = g_msum[r] + sum, totq = g_msumsq[r] + sq;
    const float mu = tot * (1.f / 512.f);
    const float rs = rsqrtf(totq * (1.f / 512.f) - mu * mu + EPS_LN);

    const size_t base = (size_t)b * 3072 + s * 512;
    float4 xv = ((const float4*)(x + (size_t)r * 128))[lane];

    // attn values from hi/lo
    const __nv_bfloat162* pah = (const __nv_bfloat162*)(g_ath + (size_t)r * 128) + lane * 2;
    const __nv_bfloat162* pal = (const __nv_bfloat162*)(g_atl + (size_t)r * 128) + lane * 2;
    float2 a01 = __bfloat1622float2(pah[0]), a23 = __bfloat1622float2(pah[1]);
    float2 l01 = __bfloat1622float2(pal[0]), l23 = __bfloat1622float2(pal[1]);
    float4 av = make_float4(a01.x + l01.x, a01.y + l01.y, a23.x + l23.x, a23.y + l23.y);

    float4 vals[4] = {n0v, n1v, xv, av};
    const int kk[4] = {4 * lane, 128 + 4 * lane, 256 + 4 * lane, 384 + 4 * lane};
#pragma unroll
    for (int q = 0; q < 4; ++q) {
        const int k = kk[q];
        float t0 = fmaf((vals[q].x - mu) * rs, g2[k],     be2[k]);
        float t1 = fmaf((vals[q].y - mu) * rs, g2[k + 1], be2[k + 1]);
        float t2 = fmaf((vals[q].z - mu) * rs, g2[k + 2], be2[k + 2]);
        float t3 = fmaf((vals[q].w - mu) * rs, g2[k + 3], be2[k + 3]);
        __nv_bfloat16 h0, l0, h1, l1, h2, l2, h3, l3;
        bf16split(t0, h0, l0); bf16split(t1, h1, l1);
        bf16split(t2, h2, l2); bf16split(t3, h3, l3);
        __nv_bfloat162 hp0 = __halves2bfloat162(h0, h1), hp1 = __halves2bfloat162(h2, h3);
        __nv_bfloat162 lp0 = __halves2bfloat162(l0, l1), lp1 = __halves2bfloat162(l2, l3);
        *(uint2*)(g_A2h + base + k) = make_uint2(*(uint32_t*)&hp0, *(uint32_t*)&hp1);
        *(uint2*)(g_A2l + base + k) = make_uint2(*(uint32_t*)&lp0, *(uint32_t*)&lp1);
    }
}

// ---------------------------------------------------------------------------
// k_out: out = relu( A2 @ Ws + bs ).  grid(x = 2 n-tiles, y = 512 m-tiles).
// ---------------------------------------------------------------------------
__global__ void __launch_bounds__(256, 2) k_out(
    const float* __restrict__ bs, float* __restrict__ out)
{
    const int n0 = blockIdx.x * 128, b0 = blockIdx.y * 128;
    gemm_cp(
        [&](int row, int k, const __nv_bfloat16*& ph, const __nv_bfloat16*& pl) {
            size_t o = (size_t)(b0 + row) * 3072 + k;
            ph = g_A2h + o; pl = g_A2l + o;
        },
        g_WsT_hi, g_WsT_lo, n0, 3072, 192,
        [&](int row, int col, float v0, float v1) {
            float2 t;
            t.x = fmaxf(v0 + bs[n0 + col], 0.f);
            t.y = fmaxf(v1 + bs[n0 + col + 1], 0.f);
            *(float2*)(out + (size_t)(b0 + row) * 256 + n0 + col) = t;
        });
}

// ---------------------------------------------------------------------------
// kernel_launch: pure kernel launches (graph-capture-safe, no host API calls)
// ---------------------------------------------------------------------------
extern "C" void kernel_launch(void* const* d_in, const int* in_sizes, int n_in,
                              void* d_out, int out_size)
{
    (void)in_sizes; (void)n_in; (void)out_size;
    const float* x   = (const float*)d_in[0];
    const float* W0  = (const float*)d_in[1];
    const float* b0  = (const float*)d_in[2];
    const float* W1  = (const float*)d_in[3];
    const float* b1  = (const float*)d_in[4];
    const float* W2  = (const float*)d_in[5];
    const float* b2  = (const float*)d_in[6];
    const float* W3  = (const float*)d_in[7];
    const float* b3  = (const float*)d_in[8];
    const float* g1  = (const float*)d_in[9];
    const float* be1 = (const float*)d_in[10];
    const float* Wf  = (const float*)d_in[11];
    const float* bf  = (const float*)d_in[12];
    const float* g2  = (const float*)d_in[13];
    const float* be2 = (const float*)d_in[14];
    const float* Ws  = (const float*)d_in[15];
    const float* bs  = (const float*)d_in[16];
    float* out = (float*)d_out;

    k_prep<<<3072, 256>>>(W0, W1, W2, W3, b0, b1, b2, b3, Wf, Ws, g1);
    k_vec<<<1, 256>>>(Wf, g1, be1, bf);
    k_cvtx<<<49152, 256>>>(x);
    k_qkv<<<dim3(3, 3072), 256>>>();
    k_attn2<<<8192, 256>>>(x);
    k_ln1<<<dim3(2, 3072), 256>>>();
    k_cvt2<<<49152, 256>>>(x, g2, be2);
    k_out<<<dim3(2, 512), 256>>>(bs, out);
}

// round 12
// speedup vs baseline: 1.3008x; 1.3008x over previous
#include <cuda_runtime.h>
#include <cuda_bf16.h>
#include <cuda_fp16.h>
#include <cstdint>

#define ROWS6 393216
#define BATCH 65536
#define EPS_LN 1e-5f

// ---------------- scratch globals (allocation-free rule) -------------------
__device__ __align__(16) float g_qkv[(size_t)ROWS6 * 384];
__device__ __align__(16) float g_n[(size_t)ROWS6 * 256];
__device__ __align__(16) __nv_bfloat16 g_xh[(size_t)ROWS6 * 128], g_xl[(size_t)ROWS6 * 128];
__device__ __align__(16) __half g_x16[(size_t)ROWS6 * 128];
__device__ __align__(16) __half g_at16[(size_t)ROWS6 * 128];
__device__ __align__(16) __half g_A2[(size_t)BATCH * 3072];
__device__ __align__(16) __nv_bfloat16 g_WcT_hi[384 * 128], g_WcT_lo[384 * 128];
__device__ __align__(16) __half g_WfT_hi[256 * 256], g_WfT_lo[256 * 256];   // g1-scaled
__device__ __align__(16) __half g_WsT_hi[256 * 3072], g_WsT_lo[256 * 3072];
__device__ float g_bc[384], g_uf[256], g_cf[256];
__device__ float g_msum[ROWS6], g_msumsq[ROWS6], g_mu1[ROWS6], g_rs1[ROWS6];

// ---------------- helpers --------------------------------------------------
__device__ __forceinline__ uint32_t smem_u32(const void* p) {
    uint32_t a;
    asm("{ .reg .u64 t; cvta.to.shared.u64 t, %1; cvt.u32.u64 %0, t; }" : "=r"(a) : "l"(p));
    return a;
}
__device__ __forceinline__ void ldsm4(uint32_t& r0, uint32_t& r1, uint32_t& r2, uint32_t& r3,
                                      uint32_t addr) {
    asm volatile("ldmatrix.sync.aligned.m8n8.x4.shared.b16 {%0,%1,%2,%3}, [%4];"
                 : "=r"(r0), "=r"(r1), "=r"(r2), "=r"(r3) : "r"(addr));
}
__device__ __forceinline__ void mma_bf16(float* d, const uint32_t* a, const uint32_t* b) {
    asm volatile("mma.sync.aligned.m16n8k16.row.col.f32.bf16.bf16.f32 "
                 "{%0,%1,%2,%3}, {%4,%5,%6,%7}, {%8,%9}, {%0,%1,%2,%3};"
                 : "+f"(d[0]), "+f"(d[1]), "+f"(d[2]), "+f"(d[3])
                 : "r"(a[0]), "r"(a[1]), "r"(a[2]), "r"(a[3]), "r"(b[0]), "r"(b[1]));
}
__device__ __forceinline__ void mma_f16(float* d, const uint32_t* a, const uint32_t* b) {
    asm volatile("mma.sync.aligned.m16n8k16.row.col.f32.f16.f16.f32 "
                 "{%0,%1,%2,%3}, {%4,%5,%6,%7}, {%8,%9}, {%0,%1,%2,%3};"
                 : "+f"(d[0]), "+f"(d[1]), "+f"(d[2]), "+f"(d[3])
                 : "r"(a[0]), "r"(a[1]), "r"(a[2]), "r"(a[3]), "r"(b[0]), "r"(b[1]));
}
__device__ __forceinline__ void cpasync16(uint32_t dst, const void* src) {
    asm volatile("cp.async.cg.shared.global [%0], [%1], 16;" :: "r"(dst), "l"(src));
}
__device__ __forceinline__ void cpcommit() {
    asm volatile("cp.async.commit_group;" ::: "memory");
}
__device__ __forceinline__ void bf16split(float v, __nv_bfloat16& h, __nv_bfloat16& l) {
    h = __float2bfloat16(v);
    l = __float2bfloat16(v - __bfloat162float(h));
}
__device__ __forceinline__ void f16split(float v, __half& h, __half& l) {
    h = __float2half(v);
    l = __float2half(v - __half2float(h));
}

// ---------------------------------------------------------------------------
// 3-term bf16 driver (k_qkv). BM=128 x BN=128, BK=16, 2-stage cp.async.
// D = ah*bh + ah*bl + al*bh.  smem 48KB.
// ---------------------------------------------------------------------------
template <class ASrc, class Epi>
__device__ __forceinline__ void gemm3(
    ASrc asrc,
    const __nv_bfloat16* __restrict__ Bh, const __nv_bfloat16* __restrict__ Bl, int n0,
    int ktot, int nchunk, Epi epi)
{
    __shared__ __align__(16) __nv_bfloat16 sm[2][4][128][24];

    const int tid = threadIdx.x, lane = tid & 31, wid = tid >> 5;
    const int m_base = (wid & 1) * 64, n_base = (wid >> 1) * 32;
    const int arow = lane & 15, acol = (lane >> 4) * 8;
    const int lrow = tid >> 1, lh = (tid & 1) * 8;

    const uint32_t s0 = smem_u32(&sm[0][0][0][0]);
    const __nv_bfloat16* gs2 = Bh + (size_t)(n0 + lrow) * ktot + lh;
    const __nv_bfloat16* gs3 = Bl + (size_t)(n0 + lrow) * ktot + lh;
    const uint32_t dstb = s0 + (uint32_t)(lrow * 24 + lh) * 2;

    float d[4][4][4];
#pragma unroll
    for (int mi = 0; mi < 4; ++mi)
#pragma unroll
        for (int ni = 0; ni < 4; ++ni)
#pragma unroll
            for (int e = 0; e < 4; ++e) d[mi][ni][e] = 0.f;

    {
        const __nv_bfloat16 *ph, *pl;
        asrc(lrow, lh, ph, pl);
        cpasync16(dstb,         ph);
        cpasync16(dstb + 6144,  pl);
        cpasync16(dstb + 12288, gs2);
        cpasync16(dstb + 18432, gs3);
        cpcommit();
        asrc(lrow, 16 + lh, ph, pl);
        cpasync16(dstb + 24576, ph);
        cpasync16(dstb + 30720, pl);
        cpasync16(dstb + 36864, gs2 + 16);
        cpasync16(dstb + 43008, gs3 + 16);
        cpcommit();
    }

    for (int c = 0; c < nchunk; ++c) {
        if (c == nchunk - 1)
            asm volatile("cp.async.wait_group 0;" ::: "memory");
        else
            asm volatile("cp.async.wait_group 1;" ::: "memory");
        __syncthreads();

        const int st = c & 1;
        const uint32_t bAh = s0 + (uint32_t)(st * 4 + 0) * 6144;
        const uint32_t bAl = s0 + (uint32_t)(st * 4 + 1) * 6144;
        const uint32_t bBh = s0 + (uint32_t)(st * 4 + 2) * 6144;
        const uint32_t bBl = s0 + (uint32_t)(st * 4 + 3) * 6144;

        uint32_t bh_[4][2], bl_[4][2];
#pragma unroll
        for (int nt = 0; nt < 2; ++nt) {
            const uint32_t off = (uint32_t)((n_base + nt * 16 + arow) * 24 + acol) * 2;
            uint32_t r0, r1, r2, r3;
            ldsm4(r0, r1, r2, r3, bBh + off);
            bh_[2 * nt][0] = r0; bh_[2 * nt][1] = r2;
            bh_[2 * nt + 1][0] = r1; bh_[2 * nt + 1][1] = r3;
            ldsm4(r0, r1, r2, r3, bBl + off);
            bl_[2 * nt][0] = r0; bl_[2 * nt][1] = r2;
            bl_[2 * nt + 1][0] = r1; bl_[2 * nt + 1][1] = r3;
        }
        uint32_t af[4][4];
#pragma unroll
        for (int mi = 0; mi < 4; ++mi) {
            const uint32_t off = (uint32_t)((m_base + mi * 16 + arow) * 24 + acol) * 2;
            ldsm4(af[mi][0], af[mi][1], af[mi][2], af[mi][3], bAh + off);
        }
#pragma unroll
        for (int mi = 0; mi < 4; ++mi)
#pragma unroll
            for (int ni = 0; ni < 4; ++ni) {
                mma_bf16(d[mi][ni], af[mi], bh_[ni]);
                mma_bf16(d[mi][ni], af[mi], bl_[ni]);
            }
#pragma unroll
        for (int mi = 0; mi < 4; ++mi) {
            const uint32_t off = (uint32_t)((m_base + mi * 16 + arow) * 24 + acol) * 2;
            ldsm4(af[mi][0], af[mi][1], af[mi][2], af[mi][3], bAl + off);
        }
#pragma unroll
        for (int mi = 0; mi < 4; ++mi)
#pragma unroll
            for (int ni = 0; ni < 4; ++ni)
                mma_bf16(d[mi][ni], af[mi], bh_[ni]);

        __syncthreads();
        if (c + 2 < nchunk) {
            const int kb = (c + 2) * 16;
            const uint32_t db = dstb + (uint32_t)(st * 4) * 6144;
            const __nv_bfloat16 *ph, *pl;
            asrc(lrow, kb + lh, ph, pl);
            cpasync16(db,         ph);
            cpasync16(db + 6144,  pl);
            cpasync16(db + 12288, gs2 + kb);
            cpasync16(db + 18432, gs3 + kb);
            cpcommit();
        } else {
            cpcommit();
        }
    }

#pragma unroll
    for (int mi = 0; mi < 4; ++mi)
#pragma unroll
        for (int ni = 0; ni < 4; ++ni) {
            const int r0 = m_base + mi * 16 + (lane >> 2);
            const int col = n_base + ni * 8 + 2 * (lane & 3);
            epi(r0, col, d[mi][ni][0], d[mi][ni][1]);
            epi(r0 + 8, col, d[mi][ni][2], d[mi][ni][3]);
        }
}

// ---------------------------------------------------------------------------
// 2-term fp16 driver (k_ln1, k_out). A single fp16, B split hi/lo fp16.
// D = a*bh + a*bl.  smem: 2 stages x 3 bufs x 128 x 24 halfs = 36.9KB.
// ---------------------------------------------------------------------------
template <class ASrc, class Epi>
__device__ __forceinline__ void gemm2(
    ASrc asrc,
    const __half* __restrict__ Bh, const __half* __restrict__ Bl, int n0,
    int ktot, int nchunk, Epi epi)
{
    __shared__ __align__(16) __half sm[2][3][128][24];

    const int tid = threadIdx.x, lane = tid & 31, wid = tid >> 5;
    const int m_base = (wid & 1) * 64, n_base = (wid >> 1) * 32;
    const int arow = lane & 15, acol = (lane >> 4) * 8;
    const int lrow = tid >> 1, lh = (tid & 1) * 8;

    const uint32_t s0 = smem_u32(&sm[0][0][0][0]);
    const __half* gs1 = Bh + (size_t)(n0 + lrow) * ktot + lh;
    const __half* gs2 = Bl + (size_t)(n0 + lrow) * ktot + lh;
    const uint32_t dstb = s0 + (uint32_t)(lrow * 24 + lh) * 2;

    float d[4][4][4];
#pragma unroll
    for (int mi = 0; mi < 4; ++mi)
#pragma unroll
        for (int ni = 0; ni < 4; ++ni)
#pragma unroll
            for (int e = 0; e < 4; ++e) d[mi][ni][e] = 0.f;

    {
        const __half* pa;
        asrc(lrow, lh, pa);
        cpasync16(dstb,         pa);
        cpasync16(dstb + 6144,  gs1);
        cpasync16(dstb + 12288, gs2);
        cpcommit();
        asrc(lrow, 16 + lh, pa);
        cpasync16(dstb + 18432, pa);
        cpasync16(dstb + 24576, gs1 + 16);
        cpasync16(dstb + 30720, gs2 + 16);
        cpcommit();
    }

    for (int c = 0; c < nchunk; ++c) {
        if (c == nchunk - 1)
            asm volatile("cp.async.wait_group 0;" ::: "memory");
        else
            asm volatile("cp.async.wait_group 1;" ::: "memory");
        __syncthreads();

        const int st = c & 1;
        const uint32_t bA  = s0 + (uint32_t)(st * 3 + 0) * 6144;
        const uint32_t bBh = s0 + (uint32_t)(st * 3 + 1) * 6144;
        const uint32_t bBl = s0 + (uint32_t)(st * 3 + 2) * 6144;

        uint32_t af[4][4];
#pragma unroll
        for (int mi = 0; mi < 4; ++mi) {
            const uint32_t off = (uint32_t)((m_base + mi * 16 + arow) * 24 + acol) * 2;
            ldsm4(af[mi][0], af[mi][1], af[mi][2], af[mi][3], bA + off);
        }
        uint32_t bf_[4][2];
#pragma unroll
        for (int nt = 0; nt < 2; ++nt) {
            const uint32_t off = (uint32_t)((n_base + nt * 16 + arow) * 24 + acol) * 2;
            uint32_t r0, r1, r2, r3;
            ldsm4(r0, r1, r2, r3, bBh + off);
            bf_[2 * nt][0] = r0; bf_[2 * nt][1] = r2;
            bf_[2 * nt + 1][0] = r1; bf_[2 * nt + 1][1] = r3;
        }
#pragma unroll
        for (int mi = 0; mi < 4; ++mi)
#pragma unroll
            for (int ni = 0; ni < 4; ++ni)
                mma_f16(d[mi][ni], af[mi], bf_[ni]);
#pragma unroll
        for (int nt = 0; nt < 2; ++nt) {
            const uint32_t off = (uint32_t)((n_base + nt * 16 + arow) * 24 + acol) * 2;
            uint32_t r0, r1, r2, r3;
            ldsm4(r0, r1, r2, r3, bBl + off);
            bf_[2 * nt][0] = r0; bf_[2 * nt][1] = r2;
            bf_[2 * nt + 1][0] = r1; bf_[2 * nt + 1][1] = r3;
        }
#pragma unroll
        for (int mi = 0; mi < 4; ++mi)
#pragma unroll
            for (int ni = 0; ni < 4; ++ni)
                mma_f16(d[mi][ni], af[mi], bf_[ni]);

        __syncthreads();
        if (c + 2 < nchunk) {
            const int kb = (c + 2) * 16;
            const uint32_t db = dstb + (uint32_t)(st * 3) * 6144;
            const __half* pa;
            asrc(lrow, kb + lh, pa);
            cpasync16(db,         pa);
            cpasync16(db + 6144,  gs1 + kb);
            cpasync16(db + 12288, gs2 + kb);
            cpcommit();
        } else {
            cpcommit();
        }
    }

#pragma unroll
    for (int mi = 0; mi < 4; ++mi)
#pragma unroll
        for (int ni = 0; ni < 4; ++ni) {
            const int r0 = m_base + mi * 16 + (lane >> 2);
            const int col = n_base + ni * 8 + 2 * (lane & 3);
            epi(r0, col, d[mi][ni][0], d[mi][ni][1]);
            epi(r0 + 8, col, d[mi][ni][2], d[mi][ni][3]);
        }
}

// ---------------------------------------------------------------------------
// k_prep: Wc -> bf16 hi/lo; Wf' (g1-folded), Ws -> fp16 hi/lo; qkv bias.
// ---------------------------------------------------------------------------
__global__ void __launch_bounds__(256) k_prep(
    const float* __restrict__ W0, const float* __restrict__ W1,
    const float* __restrict__ W2, const float* __restrict__ W3,
    const float* __restrict__ b0, const float* __restrict__ b1,
    const float* __restrict__ b2, const float* __restrict__ b3,
    const float* __restrict__ Wf, const float* __restrict__ Ws,
    const float* __restrict__ g1)
{
    const int i = blockIdx.x * 256 + threadIdx.x;
    if (i < 49152) {                       // WcT [384 n][128 k]
        int n = i >> 7, k = i & 127;
        int h = n / 96, cc = n - h * 96;
        const float* Wh = (h == 0) ? W0 : (h == 1) ? W1 : (h == 2) ? W2 : W3;
        bf16split(Wh[k * 96 + cc], g_WcT_hi[i], g_WcT_lo[i]);
    }
    if (i < 384) {
        int h = i / 96, cc = i - h * 96;
        g_bc[i] = ((h == 0) ? b0 : (h == 1) ? b1 : (h == 2) ? b2 : b3)[cc];
    }
    if (i < 65536) {                       // WfT' [256 n][256 k] = g1[k]*Wf[k][n]
        int n = i >> 8, k = i & 255;
        f16split(g1[k] * Wf[(size_t)k * 256 + n], g_WfT_hi[i], g_WfT_lo[i]);
    }
    if (i < 786432) {                      // WsT [256 n][3072 k]
        int n = i / 3072, k = i - n * 3072;
        f16split(Ws[(size_t)k * 256 + n], g_WsT_hi[i], g_WsT_lo[i]);
    }
}

// k_vec: uf[n] = sum_k g1[k]*Wf[k][n];  cf[n] = sum_k be1[k]*Wf[k][n] + bf[n].
__global__ void __launch_bounds__(256) k_vec(
    const float* __restrict__ Wf, const float* __restrict__ g1,
    const float* __restrict__ be1, const float* __restrict__ bf)
{
    const int n = threadIdx.x;
    float u = 0.f, c = 0.f;
    for (int k = 0; k < 256; ++k) {
        float w = Wf[(size_t)k * 256 + n];
        u = fmaf(g1[k], w, u);
        c = fmaf(be1[k], w, c);
    }
    g_uf[n] = u;
    g_cf[n] = c + bf[n];
}

// ---------------------------------------------------------------------------
// k_cvtx: x fp32 -> bf16 hi/lo (qkv A) + fp16 single (ln1 A).
// ---------------------------------------------------------------------------
__global__ void __launch_bounds__(256) k_cvtx(const float* __restrict__ x)
{
    const size_t i = (size_t)blockIdx.x * 256 + threadIdx.x;   // float4 index
    float4 v = ((const float4*)x)[i];
    __nv_bfloat16 h0, l0, h1, l1, h2, l2, h3, l3;
    bf16split(v.x, h0, l0); bf16split(v.y, h1, l1);
    bf16split(v.z, h2, l2); bf16split(v.w, h3, l3);
    __nv_bfloat162 hp0 = __halves2bfloat162(h0, h1), hp1 = __halves2bfloat162(h2, h3);
    __nv_bfloat162 lp0 = __halves2bfloat162(l0, l1), lp1 = __halves2bfloat162(l2, l3);
    ((uint2*)g_xh)[i] = make_uint2(*(uint32_t*)&hp0, *(uint32_t*)&hp1);
    ((uint2*)g_xl)[i] = make_uint2(*(uint32_t*)&lp0, *(uint32_t*)&lp1);
    __half2 q0 = __floats2half2_rn(v.x, v.y), q1 = __floats2half2_rn(v.z, v.w);
    ((uint2*)g_x16)[i] = make_uint2(*(uint32_t*)&q0, *(uint32_t*)&q1);
}

// ---------------------------------------------------------------------------
// k_qkv: g_qkv = x @ Wcat + bcat.  grid(x = 3 n-tiles, y = 3072 m-tiles).
// ---------------------------------------------------------------------------
__global__ void __launch_bounds__(256, 2) k_qkv()
{
    const int n0 = blockIdx.x * 128, row0 = blockIdx.y * 128;
    gemm3(
        [&](int row, int k, const __nv_bfloat16*& ph, const __nv_bfloat16*& pl) {
            size_t o = (size_t)(row0 + row) * 128 + k;
            ph = g_xh + o; pl = g_xl + o;
        },
        g_WcT_hi, g_WcT_lo, n0, 128, 8,
        [&](int row, int col, float v0, float v1) {
            float2 t;
            t.x = v0 + g_bc[n0 + col];
            t.y = v1 + g_bc[n0 + col + 1];
            *(float2*)(g_qkv + (size_t)(row0 + row) * 384 + n0 + col) = t;
        });
}

// ---------------------------------------------------------------------------
// k_attn2: attention -> attn fp16 + m stats + mu1/rs1.
// ---------------------------------------------------------------------------
__global__ void __launch_bounds__(256) k_attn2(const float* __restrict__ x)
{
    const int tid = threadIdx.x, w = tid >> 5, lane = tid & 31;
    const int b = blockIdx.x * 8 + w;

    float qv[6][12];
#pragma unroll
    for (int s = 0; s < 6; ++s)
#pragma unroll
        for (int jj = 0; jj < 12; ++jj)
            qv[s][jj] = g_qkv[((size_t)b * 6 + s) * 384 + jj * 32 + lane];

    float ssum[6], ssq[6];
#pragma unroll
    for (int s = 0; s < 6; ++s) {
        float a = 0.f, q = 0.f;
#pragma unroll
        for (int i = 0; i < 4; ++i) {
            float v = x[(size_t)b * 768 + s * 128 + lane + 32 * i];
            a += v; q += v * v;
        }
        ssum[s] = a; ssq[s] = q;
    }

#pragma unroll
    for (int h = 0; h < 4; ++h) {
#pragma unroll
        for (int qi = 0; qi < 6; ++qi) {
            float o = 0.f;
#pragma unroll
            for (int ki = 0; ki < 6; ++ki) {
                float p = qv[qi][3 * h] * qv[ki][3 * h + 1];
#pragma unroll
                for (int off = 16; off > 0; off >>= 1)
                    p += __shfl_xor_sync(0xffffffffu, p, off);
                o = fmaf(p, qv[ki][3 * h + 2], o);
            }
            g_at16[((size_t)b * 6 + qi) * 128 + h * 32 + lane] = __float2half(o);
            ssum[qi] += o;
            ssq[qi] += o * o;
        }
    }

#pragma unroll
    for (int s = 0; s < 6; ++s) {
        float a = ssum[s], q = ssq[s];
#pragma unroll
        for (int off = 16; off > 0; off >>= 1) {
            a += __shfl_xor_sync(0xffffffffu, a, off);
            q += __shfl_xor_sync(0xffffffffu, q, off);
        }
        if (lane == 0) {
            const int r = b * 6 + s;
            g_msum[r] = a;
            g_msumsq[r] = q;
            const float mu = a * (1.f / 256.f);
            const float var = q * (1.f / 256.f) - mu * mu;
            g_mu1[r] = mu;
            g_rs1[r] = rsqrtf(var + EPS_LN);
        }
    }
}

// ---------------------------------------------------------------------------
// k_ln1: g_n = rs1*( m @ Wf' - mu1*uf ) + cf.   A = fp16 m (x | attn).
// grid(x = 2 n-tiles, y = 3072 m-tiles).
// ---------------------------------------------------------------------------
__global__ void __launch_bounds__(256, 2) k_ln1()
{
    const int n0 = blockIdx.x * 128, row0 = blockIdx.y * 128;
    gemm2(
        [&](int row, int k, const __half*& pa) {
            const size_t r = (size_t)(row0 + row);
            pa = (k < 128) ? g_x16 + r * 128 + k : g_at16 + r * 128 + (k - 128);
        },
        g_WfT_hi, g_WfT_lo, n0, 256, 16,
        [&](int row, int col, float v0, float v1) {
            const int r = row0 + row;
            const float mu = g_mu1[r], rs = g_rs1[r];
            const int c0 = n0 + col;
            float2 t;
            t.x = rs * (v0 - mu * g_uf[c0])     + g_cf[c0];
            t.y = rs * (v1 - mu * g_uf[c0 + 1]) + g_cf[c0 + 1];
            *(float2*)(g_n + (size_t)r * 256 + c0) = t;
        });
}

// ---------------------------------------------------------------------------
// k_cvt2: LN2 stats over concat(n,m) + write A2 fp16 (g2/be2 folded).
// One warp per row r = b*6+s.  A2 k-order per row: [n 256][x 128][attn 128].
// ---------------------------------------------------------------------------
__global__ void __launch_bounds__(256) k_cvt2(
    const float* __restrict__ x,
    const float* __restrict__ g2, const float* __restrict__ be2)
{
    const int w = threadIdx.x >> 5, lane = threadIdx.x & 31;
    const int r = blockIdx.x * 8 + w;
    const int b = r / 6, s = r - b * 6;

    const float4* pn = (const float4*)(g_n + (size_t)r * 256);
    float4 n0v = pn[lane], n1v = pn[32 + lane];
    float sum = n0v.x + n0v.y + n0v.z + n0v.w + n1v.x + n1v.y + n1v.z + n1v.w;
    float sq  = n0v.x * n0v.x + n0v.y * n0v.y + n0v.z * n0v.z + n0v.w * n0v.w
              + n1v.x * n1v.x + n1v.y * n1v.y + n1v.z * n1v.z + n1v.w * n1v.w;
#pragma unroll
    for (int off = 16; off > 0; off >>= 1) {
        sum += __shfl_xor_sync(0xffffffffu, sum, off);
        sq  += __shfl_xor_sync(0xffffffffu, sq, off);
    }
    const float tot = g_msum[r] + sum, totq = g_msumsq[r] + sq;
    const float mu = tot * (1.f / 512.f);
    const float rs = rsqrtf(totq * (1.f / 512.f) - mu * mu + EPS_LN);

    const size_t base = (size_t)b * 3072 + s * 512;
    float4 xv = ((const float4*)(x + (size_t)r * 128))[lane];

    uint2 ar = *(const uint2*)(g_at16 + (size_t)r * 128 + 4 * lane);
    float2 a01 = __half22float2(*(__half2*)&ar.x), a23 = __half22float2(*(__half2*)&ar.y);
    float4 av = make_float4(a01.x, a01.y, a23.x, a23.y);

    float4 vals[4] = {n0v, n1v, xv, av};
    const int kk[4] = {4 * lane, 128 + 4 * lane, 256 + 4 * lane, 384 + 4 * lane};
#pragma unroll
    for (int q = 0; q < 4; ++q) {
        const int k = kk[q];
        float t0 = fmaf((vals[q].x - mu) * rs, g2[k],     be2[k]);
        float t1 = fmaf((vals[q].y - mu) * rs, g2[k + 1], be2[k + 1]);
        float t2 = fmaf((vals[q].z - mu) * rs, g2[k + 2], be2[k + 2]);
        float t3 = fmaf((vals[q].w - mu) * rs, g2[k + 3], be2[k + 3]);
        __half2 p0 = __floats2half2_rn(t0, t1), p1 = __floats2half2_rn(t2, t3);
        *(uint2*)(g_A2 + base + k) = make_uint2(*(uint32_t*)&p0, *(uint32_t*)&p1);
    }
}

// ---------------------------------------------------------------------------
// k_out: out = relu( A2 @ Ws + bs ).  grid(x = 2 n-tiles, y = 512 m-tiles).
// ---------------------------------------------------------------------------
__global__ void __launch_bounds__(256, 2) k_out(
    const float* __restrict__ bs, float* __restrict__ out)
{
    const int n0 = blockIdx.x * 128, b0 = blockIdx.y * 128;
    gemm2(
        [&](int row, int k, const __half*& pa) {
            pa = g_A2 + (size_t)(b0 + row) * 3072 + k;
        },
        g_WsT_hi, g_WsT_lo, n0, 3072, 192,
        [&](int row, int col, float v0, float v1) {
            float2 t;
            t.x = fmaxf(v0 + bs[n0 + col], 0.f);
            t.y = fmaxf(v1 + bs[n0 + col + 1], 0.f);
            *(float2*)(out + (size_t)(b0 + row) * 256 + n0 + col) = t;
        });
}

// ---------------------------------------------------------------------------
// kernel_launch: pure kernel launches (graph-capture-safe, no host API calls)
// ---------------------------------------------------------------------------
extern "C" void kernel_launch(void* const* d_in, const int* in_sizes, int n_in,
                              void* d_out, int out_size)
{
    (void)in_sizes; (void)n_in; (void)out_size;
    const float* x   = (const float*)d_in[0];
    const float* W0  = (const float*)d_in[1];
    const float* b0  = (const float*)d_in[2];
    const float* W1  = (const float*)d_in[3];
    const float* b1  = (const float*)d_in[4];
    const float* W2  = (const float*)d_in[5];
    const float* b2  = (const float*)d_in[6];
    const float* W3  = (const float*)d_in[7];
    const float* b3  = (const float*)d_in[8];
    const float* g1  = (const float*)d_in[9];
    const float* be1 = (const float*)d_in[10];
    const float* Wf  = (const float*)d_in[11];
    const float* bf  = (const float*)d_in[12];
    const float* g2  = (const float*)d_in[13];
    const float* be2 = (const float*)d_in[14];
    const float* Ws  = (const float*)d_in[15];
    const float* bs  = (const float*)d_in[16];
    float* out = (float*)d_out;

    k_prep<<<3072, 256>>>(W0, W1, W2, W3, b0, b1, b2, b3, Wf, Ws, g1);
    k_vec<<<1, 256>>>(Wf, g1, be1, bf);
    k_cvtx<<<49152, 256>>>(x);
    k_qkv<<<dim3(3, 3072), 256>>>();
    k_attn2<<<8192, 256>>>(x);
    k_ln1<<<dim3(2, 3072), 256>>>();
    k_cvt2<<<49152, 256>>>(x, g2, be2);
    k_out<<<dim3(2, 512), 256>>>(bs, out);
}

// round 13
// speedup vs baseline: 1.3727x; 1.0553x over previous
#include <cuda_runtime.h>
#include <cuda_bf16.h>
#include <cuda_fp16.h>
#include <cstdint>

#define ROWS6 393216
#define BATCH 65536
#define EPS_LN 1e-5f

// ---------------- scratch globals (allocation-free rule) -------------------
__device__ __align__(16) __half g_qkv[(size_t)ROWS6 * 384];
__device__ __align__(16) __half g_n[(size_t)ROWS6 * 256];
__device__ __align__(16) __half g_x16[(size_t)ROWS6 * 128];
__device__ __align__(16) __half g_at16[(size_t)ROWS6 * 128];
__device__ __align__(16) __half g_A2[(size_t)BATCH * 3072];
__device__ __align__(16) __half g_WcT_hi[384 * 128], g_WcT_lo[384 * 128];
__device__ __align__(16) __half g_WfT_hi[256 * 256], g_WfT_lo[256 * 256];   // g1-scaled
__device__ __align__(16) __half g_WsT_hi[256 * 3072], g_WsT_lo[256 * 3072];
__device__ float g_bc[384], g_uf[256], g_cf[256];
__device__ float g_msum[ROWS6], g_msumsq[ROWS6], g_mu1[ROWS6], g_rs1[ROWS6];

// ---------------- helpers --------------------------------------------------
__device__ __forceinline__ uint32_t smem_u32(const void* p) {
    uint32_t a;
    asm("{ .reg .u64 t; cvta.to.shared.u64 t, %1; cvt.u32.u64 %0, t; }" : "=r"(a) : "l"(p));
    return a;
}
__device__ __forceinline__ void ldsm4(uint32_t& r0, uint32_t& r1, uint32_t& r2, uint32_t& r3,
                                      uint32_t addr) {
    asm volatile("ldmatrix.sync.aligned.m8n8.x4.shared.b16 {%0,%1,%2,%3}, [%4];"
                 : "=r"(r0), "=r"(r1), "=r"(r2), "=r"(r3) : "r"(addr));
}
__device__ __forceinline__ void mma_f16(float* d, const uint32_t* a, const uint32_t* b) {
    asm volatile("mma.sync.aligned.m16n8k16.row.col.f32.f16.f16.f32 "
                 "{%0,%1,%2,%3}, {%4,%5,%6,%7}, {%8,%9}, {%0,%1,%2,%3};"
                 : "+f"(d[0]), "+f"(d[1]), "+f"(d[2]), "+f"(d[3])
                 : "r"(a[0]), "r"(a[1]), "r"(a[2]), "r"(a[3]), "r"(b[0]), "r"(b[1]));
}
__device__ __forceinline__ void cpasync16(uint32_t dst, const void* src) {
    asm volatile("cp.async.cg.shared.global [%0], [%1], 16;" :: "r"(dst), "l"(src));
}
__device__ __forceinline__ void cpcommit() {
    asm volatile("cp.async.commit_group;" ::: "memory");
}
__device__ __forceinline__ void f16split(float v, __half& h, __half& l) {
    h = __float2half(v);
    l = __float2half(v - __half2float(h));
}

// ---------------------------------------------------------------------------
// 2-term fp16 driver. A single fp16, B split hi/lo fp16.
// BM=128 x BN=128, BK=16, 2-stage cp.async.  D = a*bh + a*bl.
// smem: 2 stages x 3 bufs x 128 x 24 halfs = 36.9KB.  2 CTAs/SM.
// ---------------------------------------------------------------------------
template <class ASrc, class Epi>
__device__ __forceinline__ void gemm2(
    ASrc asrc,
    const __half* __restrict__ Bh, const __half* __restrict__ Bl, int n0,
    int ktot, int nchunk, Epi epi)
{
    __shared__ __align__(16) __half sm[2][3][128][24];

    const int tid = threadIdx.x, lane = tid & 31, wid = tid >> 5;
    const int m_base = (wid & 1) * 64, n_base = (wid >> 1) * 32;
    const int arow = lane & 15, acol = (lane >> 4) * 8;
    const int lrow = tid >> 1, lh = (tid & 1) * 8;

    const uint32_t s0 = smem_u32(&sm[0][0][0][0]);
    const __half* gs1 = Bh + (size_t)(n0 + lrow) * ktot + lh;
    const __half* gs2 = Bl + (size_t)(n0 + lrow) * ktot + lh;
    const uint32_t dstb = s0 + (uint32_t)(lrow * 24 + lh) * 2;

    float d[4][4][4];
#pragma unroll
    for (int mi = 0; mi < 4; ++mi)
#pragma unroll
        for (int ni = 0; ni < 4; ++ni)
#pragma unroll
            for (int e = 0; e < 4; ++e) d[mi][ni][e] = 0.f;

    {
        const __half* pa;
        asrc(lrow, lh, pa);
        cpasync16(dstb,         pa);
        cpasync16(dstb + 6144,  gs1);
        cpasync16(dstb + 12288, gs2);
        cpcommit();
        asrc(lrow, 16 + lh, pa);
        cpasync16(dstb + 18432, pa);
        cpasync16(dstb + 24576, gs1 + 16);
        cpasync16(dstb + 30720, gs2 + 16);
        cpcommit();
    }

    for (int c = 0; c < nchunk; ++c) {
        if (c == nchunk - 1)
            asm volatile("cp.async.wait_group 0;" ::: "memory");
        else
            asm volatile("cp.async.wait_group 1;" ::: "memory");
        __syncthreads();

        const int st = c & 1;
        const uint32_t bA  = s0 + (uint32_t)(st * 3 + 0) * 6144;
        const uint32_t bBh = s0 + (uint32_t)(st * 3 + 1) * 6144;
        const uint32_t bBl = s0 + (uint32_t)(st * 3 + 2) * 6144;

        uint32_t af[4][4];
#pragma unroll
        for (int mi = 0; mi < 4; ++mi) {
            const uint32_t off = (uint32_t)((m_base + mi * 16 + arow) * 24 + acol) * 2;
            ldsm4(af[mi][0], af[mi][1], af[mi][2], af[mi][3], bA + off);
        }
        uint32_t bf_[4][2];
#pragma unroll
        for (int nt = 0; nt < 2; ++nt) {
            const uint32_t off = (uint32_t)((n_base + nt * 16 + arow) * 24 + acol) * 2;
            uint32_t r0, r1, r2, r3;
            ldsm4(r0, r1, r2, r3, bBh + off);
            bf_[2 * nt][0] = r0; bf_[2 * nt][1] = r2;
            bf_[2 * nt + 1][0] = r1; bf_[2 * nt + 1][1] = r3;
        }
#pragma unroll
        for (int mi = 0; mi < 4; ++mi)
#pragma unroll
            for (int ni = 0; ni < 4; ++ni)
                mma_f16(d[mi][ni], af[mi], bf_[ni]);
#pragma unroll
        for (int nt = 0; nt < 2; ++nt) {
            const uint32_t off = (uint32_t)((n_base + nt * 16 + arow) * 24 + acol) * 2;
            uint32_t r0, r1, r2, r3;
            ldsm4(r0, r1, r2, r3, bBl + off);
            bf_[2 * nt][0] = r0; bf_[2 * nt][1] = r2;
            bf_[2 * nt + 1][0] = r1; bf_[2 * nt + 1][1] = r3;
        }
#pragma unroll
        for (int mi = 0; mi < 4; ++mi)
#pragma unroll
            for (int ni = 0; ni < 4; ++ni)
                mma_f16(d[mi][ni], af[mi], bf_[ni]);

        __syncthreads();
        if (c + 2 < nchunk) {
            const int kb = (c + 2) * 16;
            const uint32_t db = dstb + (uint32_t)(st * 3) * 6144;
            const __half* pa;
            asrc(lrow, kb + lh, pa);
            cpasync16(db,         pa);
            cpasync16(db + 6144,  gs1 + kb);
            cpasync16(db + 12288, gs2 + kb);
            cpcommit();
        } else {
            cpcommit();
        }
    }

#pragma unroll
    for (int mi = 0; mi < 4; ++mi)
#pragma unroll
        for (int ni = 0; ni < 4; ++ni) {
            const int r0 = m_base + mi * 16 + (lane >> 2);
            const int col = n_base + ni * 8 + 2 * (lane & 3);
            epi(r0, col, d[mi][ni][0], d[mi][ni][1]);
            epi(r0 + 8, col, d[mi][ni][2], d[mi][ni][3]);
        }
}

// ---------------------------------------------------------------------------
// k_prep: Wc, Wf' (g1-folded), Ws -> fp16 hi/lo; qkv bias.
// ---------------------------------------------------------------------------
__global__ void __launch_bounds__(256) k_prep(
    const float* __restrict__ W0, const float* __restrict__ W1,
    const float* __restrict__ W2, const float* __restrict__ W3,
    const float* __restrict__ b0, const float* __restrict__ b1,
    const float* __restrict__ b2, const float* __restrict__ b3,
    const float* __restrict__ Wf, const float* __restrict__ Ws,
    const float* __restrict__ g1)
{
    const int i = blockIdx.x * 256 + threadIdx.x;
    if (i < 49152) {                       // WcT [384 n][128 k]
        int n = i >> 7, k = i & 127;
        int h = n / 96, cc = n - h * 96;
        const float* Wh = (h == 0) ? W0 : (h == 1) ? W1 : (h == 2) ? W2 : W3;
        f16split(Wh[k * 96 + cc], g_WcT_hi[i], g_WcT_lo[i]);
    }
    if (i < 384) {
        int h = i / 96, cc = i - h * 96;
        g_bc[i] = ((h == 0) ? b0 : (h == 1) ? b1 : (h == 2) ? b2 : b3)[cc];
    }
    if (i < 65536) {                       // WfT' [256 n][256 k] = g1[k]*Wf[k][n]
        int n = i >> 8, k = i & 255;
        f16split(g1[k] * Wf[(size_t)k * 256 + n], g_WfT_hi[i], g_WfT_lo[i]);
    }
    if (i < 786432) {                      // WsT [256 n][3072 k]
        int n = i / 3072, k = i - n * 3072;
        f16split(Ws[(size_t)k * 256 + n], g_WsT_hi[i], g_WsT_lo[i]);
    }
}

// k_vec: uf[n] = sum_k g1[k]*Wf[k][n];  cf[n] = sum_k be1[k]*Wf[k][n] + bf[n].
__global__ void __launch_bounds__(256) k_vec(
    const float* __restrict__ Wf, const float* __restrict__ g1,
    const float* __restrict__ be1, const float* __restrict__ bf)
{
    const int n = threadIdx.x;
    float u = 0.f, c = 0.f;
    for (int k = 0; k < 256; ++k) {
        float w = Wf[(size_t)k * 256 + n];
        u = fmaf(g1[k], w, u);
        c = fmaf(be1[k], w, c);
    }
    g_uf[n] = u;
    g_cf[n] = c + bf[n];
}

// ---------------------------------------------------------------------------
// k_cvtx: x fp32 -> fp16.
// ---------------------------------------------------------------------------
__global__ void __launch_bounds__(256) k_cvtx(const float* __restrict__ x)
{
    const size_t i = (size_t)blockIdx.x * 256 + threadIdx.x;   // float4 index
    float4 v = ((const float4*)x)[i];
    __half2 q0 = __floats2half2_rn(v.x, v.y), q1 = __floats2half2_rn(v.z, v.w);
    ((uint2*)g_x16)[i] = make_uint2(*(uint32_t*)&q0, *(uint32_t*)&q1);
}

// ---------------------------------------------------------------------------
// k_qkv: g_qkv = fp16( x @ Wcat + bcat ).  grid(x = 3 n-tiles, y = 3072 m).
// ---------------------------------------------------------------------------
__global__ void __launch_bounds__(256, 2) k_qkv()
{
    const int n0 = blockIdx.x * 128, row0 = blockIdx.y * 128;
    gemm2(
        [&](int row, int k, const __half*& pa) {
            pa = g_x16 + (size_t)(row0 + row) * 128 + k;
        },
        g_WcT_hi, g_WcT_lo, n0, 128, 8,
        [&](int row, int col, float v0, float v1) {
            __half2 t = __floats2half2_rn(v0 + g_bc[n0 + col], v1 + g_bc[n0 + col + 1]);
            *(__half2*)(g_qkv + (size_t)(row0 + row) * 384 + n0 + col) = t;
        });
}

// ---------------------------------------------------------------------------
// k_attn2: attention -> attn fp16 + m stats + mu1/rs1.  qkv read as fp16.
// ---------------------------------------------------------------------------
__global__ void __launch_bounds__(256) k_attn2(const float* __restrict__ x)
{
    const int tid = threadIdx.x, w = tid >> 5, lane = tid & 31;
    const int b = blockIdx.x * 8 + w;

    float qv[6][12];
#pragma unroll
    for (int s = 0; s < 6; ++s)
#pragma unroll
        for (int jj = 0; jj < 12; ++jj)
            qv[s][jj] = __half2float(g_qkv[((size_t)b * 6 + s) * 384 + jj * 32 + lane]);

    float ssum[6], ssq[6];
#pragma unroll
    for (int s = 0; s < 6; ++s) {
        float a = 0.f, q = 0.f;
#pragma unroll
        for (int i = 0; i < 4; ++i) {
            float v = x[(size_t)b * 768 + s * 128 + lane + 32 * i];
            a += v; q += v * v;
        }
        ssum[s] = a; ssq[s] = q;
    }

#pragma unroll
    for (int h = 0; h < 4; ++h) {
#pragma unroll
        for (int qi = 0; qi < 6; ++qi) {
            float o = 0.f;
#pragma unroll
            for (int ki = 0; ki < 6; ++ki) {
                float p = qv[qi][3 * h] * qv[ki][3 * h + 1];
#pragma unroll
                for (int off = 16; off > 0; off >>= 1)
                    p += __shfl_xor_sync(0xffffffffu, p, off);
                o = fmaf(p, qv[ki][3 * h + 2], o);
            }
            g_at16[((size_t)b * 6 + qi) * 128 + h * 32 + lane] = __float2half(o);
            ssum[qi] += o;
            ssq[qi] += o * o;
        }
    }

#pragma unroll
    for (int s = 0; s < 6; ++s) {
        float a = ssum[s], q = ssq[s];
#pragma unroll
        for (int off = 16; off > 0; off >>= 1) {
            a += __shfl_xor_sync(0xffffffffu, a, off);
            q += __shfl_xor_sync(0xffffffffu, q, off);
        }
        if (lane == 0) {
            const int r = b * 6 + s;
            g_msum[r] = a;
            g_msumsq[r] = q;
            const float mu = a * (1.f / 256.f);
            const float var = q * (1.f / 256.f) - mu * mu;
            g_mu1[r] = mu;
            g_rs1[r] = rsqrtf(var + EPS_LN);
        }
    }
}

// ---------------------------------------------------------------------------
// k_ln1: g_n = fp16( rs1*( m @ Wf' - mu1*uf ) + cf ).   A = fp16 m (x | attn).
// grid(x = 2 n-tiles, y = 3072 m-tiles).
// ---------------------------------------------------------------------------
__global__ void __launch_bounds__(256, 2) k_ln1()
{
    const int n0 = blockIdx.x * 128, row0 = blockIdx.y * 128;
    gemm2(
        [&](int row, int k, const __half*& pa) {
            const size_t r = (size_t)(row0 + row);
            pa = (k < 128) ? g_x16 + r * 128 + k : g_at16 + r * 128 + (k - 128);
        },
        g_WfT_hi, g_WfT_lo, n0, 256, 16,
        [&](int row, int col, float v0, float v1) {
            const int r = row0 + row;
            const float mu = g_mu1[r], rs = g_rs1[r];
            const int c0 = n0 + col;
            float t0 = rs * (v0 - mu * g_uf[c0])     + g_cf[c0];
            float t1 = rs * (v1 - mu * g_uf[c0 + 1]) + g_cf[c0 + 1];
            *(__half2*)(g_n + (size_t)r * 256 + c0) = __floats2half2_rn(t0, t1);
        });
}

// ---------------------------------------------------------------------------
// k_cvt2: LN2 stats over concat(n,m) + write A2 fp16 (g2/be2 folded).
// One warp per row r = b*6+s.  A2 k-order per row: [n 256][x 128][attn 128].
// ---------------------------------------------------------------------------
__global__ void __launch_bounds__(256) k_cvt2(
    const float* __restrict__ x,
    const float* __restrict__ g2, const float* __restrict__ be2)
{
    const int w = threadIdx.x >> 5, lane = threadIdx.x & 31;
    const int r = blockIdx.x * 8 + w;
    const int b = r / 6, s = r - b * 6;

    // n: 8 halfs per lane (uint4)
    uint4 nv4 = *(const uint4*)(g_n + (size_t)r * 256 + 8 * lane);
    float2 n01 = __half22float2(*(__half2*)&nv4.x);
    float2 n23 = __half22float2(*(__half2*)&nv4.y);
    float2 n45 = __half22float2(*(__half2*)&nv4.z);
    float2 n67 = __half22float2(*(__half2*)&nv4.w);
    float nv[8] = {n01.x, n01.y, n23.x, n23.y, n45.x, n45.y, n67.x, n67.y};

    float sum = 0.f, sq = 0.f;
#pragma unroll
    for (int i = 0; i < 8; ++i) { sum += nv[i]; sq += nv[i] * nv[i]; }
#pragma unroll
    for (int off = 16; off > 0; off >>= 1) {
        sum += __shfl_xor_sync(0xffffffffu, sum, off);
        sq  += __shfl_xor_sync(0xffffffffu, sq, off);
    }
    const float tot = g_msum[r] + sum, totq = g_msumsq[r] + sq;
    const float mu = tot * (1.f / 512.f);
    const float rs = rsqrtf(totq * (1.f / 512.f) - mu * mu + EPS_LN);

    const size_t base = (size_t)b * 3072 + s * 512;

    // n part: k = 8*lane .. 8*lane+7
    {
        const int k0 = 8 * lane;
        __half hv[8];
#pragma unroll
        for (int i = 0; i < 8; ++i)
            hv[i] = __float2half(fmaf((nv[i] - mu) * rs, g2[k0 + i], be2[k0 + i]));
        uint4 o;
        __half2 p0 = __halves2half2(hv[0], hv[1]), p1 = __halves2half2(hv[2], hv[3]);
        __half2 p2 = __halves2half2(hv[4], hv[5]), p3 = __halves2half2(hv[6], hv[7]);
        o.x = *(uint32_t*)&p0; o.y = *(uint32_t*)&p1;
        o.z = *(uint32_t*)&p2; o.w = *(uint32_t*)&p3;
        *(uint4*)(g_A2 + base + k0) = o;
    }
    // x part: k = 256 + 4*lane
    {
        float4 xv = ((const float4*)(x + (size_t)r * 128))[lane];
        const int k = 256 + 4 * lane;
        __half2 p0 = __floats2half2_rn(fmaf((xv.x - mu) * rs, g2[k],     be2[k]),
                                       fmaf((xv.y - mu) * rs, g2[k + 1], be2[k + 1]));
        __half2 p1 = __floats2half2_rn(fmaf((xv.z - mu) * rs, g2[k + 2], be2[k + 2]),
                                       fmaf((xv.w - mu) * rs, g2[k + 3], be2[k + 3]));
        *(uint2*)(g_A2 + base + k) = make_uint2(*(uint32_t*)&p0, *(uint32_t*)&p1);
    }
    // attn part: k = 384 + 4*lane
    {
        uint2 ar = *(const uint2*)(g_at16 + (size_t)r * 128 + 4 * lane);
        float2 a01 = __half22float2(*(__half2*)&ar.x), a23 = __half22float2(*(__half2*)&ar.y);
        const int k = 384 + 4 * lane;
        __half2 p0 = __floats2half2_rn(fmaf((a01.x - mu) * rs, g2[k],     be2[k]),
                                       fmaf((a01.y - mu) * rs, g2[k + 1], be2[k + 1]));
        __half2 p1 = __floats2half2_rn(fmaf((a23.x - mu) * rs, g2[k + 2], be2[k + 2]),
                                       fmaf((a23.y - mu) * rs, g2[k + 3], be2[k + 3]));
        *(uint2*)(g_A2 + base + k) = make_uint2(*(uint32_t*)&p0, *(uint32_t*)&p1);
    }
}

// ---------------------------------------------------------------------------
// k_out: out = relu( A2 @ Ws + bs ).  grid(x = 2 n-tiles, y = 512 m-tiles).
// ---------------------------------------------------------------------------
__global__ void __launch_bounds__(256, 2) k_out(
    const float* __restrict__ bs, float* __restrict__ out)
{
    const int n0 = blockIdx.x * 128, b0 = blockIdx.y * 128;
    gemm2(
        [&](int row, int k, const __half*& pa) {
            pa = g_A2 + (size_t)(b0 + row) * 3072 + k;
        },
        g_WsT_hi, g_WsT_lo, n0, 3072, 192,
        [&](int row, int col, float v0, float v1) {
            float2 t;
            t.x = fmaxf(v0 + bs[n0 + col], 0.f);
            t.y = fmaxf(v1 + bs[n0 + col + 1], 0.f);
            *(float2*)(out + (size_t)(b0 + row) * 256 + n0 + col) = t;
        });
}

// ---------------------------------------------------------------------------
// kernel_launch: pure kernel launches (graph-capture-safe, no host API calls)
// ---------------------------------------------------------------------------
extern "C" void kernel_launch(void* const* d_in, const int* in_sizes, int n_in,
                              void* d_out, int out_size)
{
    (void)in_sizes; (void)n_in; (void)out_size;
    const float* x   = (const float*)d_in[0];
    const float* W0  = (const float*)d_in[1];
    const float* b0  = (const float*)d_in[2];
    const float* W1  = (const float*)d_in[3];
    const float* b1  = (const float*)d_in[4];
    const float* W2  = (const float*)d_in[5];
    const float* b2  = (const float*)d_in[6];
    const float* W3  = (const float*)d_in[7];
    const float* b3  = (const float*)d_in[8];
    const float* g1  = (const float*)d_in[9];
    const float* be1 = (const float*)d_in[10];
    const float* Wf  = (const float*)d_in[11];
    const float* bf  = (const float*)d_in[12];
    const float* g2  = (const float*)d_in[13];
    const float* be2 = (const float*)d_in[14];
    const float* Ws  = (const float*)d_in[15];
    const float* bs  = (const float*)d_in[16];
    float* out = (float*)d_out;

    k_prep<<<3072, 256>>>(W0, W1, W2, W3, b0, b1, b2, b3, Wf, Ws, g1);
    k_vec<<<1, 256>>>(Wf, g1, be1, bf);
    k_cvtx<<<49152, 256>>>(x);
    k_qkv<<<dim3(3, 3072), 256>>>();
    k_attn2<<<8192, 256>>>(x);
    k_ln1<<<dim3(2, 3072), 256>>>();
    k_cvt2<<<49152, 256>>>(x, g2, be2);
    k_out<<<dim3(2, 512), 256>>>(bs, out);
}